// round 14
// baseline (speedup 1.0000x reference)
#include <cuda_runtime.h>
#include <cstdint>

// Cumulative matrix product over axis 1; inputs are I + 0.02*noise.
// Identity-subtracted scan: every matmul computes only D_a @ D_b (deviations),
// with fp16 1-term MMA in pass1/pass3 (error ~ 2^-12*sa*sb*sqrt(128), tiny),
// and the proven 3-term fp16 core for the chunk-total scan (pass2).

#define DN 128
#define BATCH 32
#define SEQ 256
#define CH 16
#define CL 16
#define MM ((size_t)DN * DN)

#define AROWB 272u  // smem row: 128 halves + 8 pad (conflict-free ldmatrix)
// pass1 dynamic smem: resident Dp hi/lo + one k16 slab of De(hi)
#define OFF_PH 0u
#define OFF_PL 34816u
#define OFF_E1 69632u
#define P1_SMEM 73984
// pass3 dynamic smem: resident Dc hi + one k16 slab of Dl(hi)
#define OFF_CHI 0u
#define OFF_E3 34816u
#define P3_SMEM 39168

__device__ float g_scr0[(size_t)BATCH * CH * DN * DN];
__device__ float g_scr1[(size_t)BATCH * CH * DN * DN];

__device__ __forceinline__ unsigned smem_u32(const void* p) {
    unsigned a;
    asm("{ .reg .u64 t; cvta.to.shared.u64 t, %1; cvt.u32.u64 %0, t; }" : "=r"(a) : "l"(p));
    return a;
}
__device__ __forceinline__ unsigned pack2h(float lo, float hi) {
    unsigned r;
    asm("cvt.rn.f16x2.f32 %0, %1, %2;" : "=r"(r) : "f"(hi), "f"(lo));
    return r;
}
__device__ __forceinline__ float2 h2f(unsigned h) {
    float2 f;
    asm("{ .reg .f16 a, b;\n\t mov.b32 {a, b}, %2;\n\t"
        " cvt.f32.f16 %0, a;\n\t cvt.f32.f16 %1, b; }"
        : "=f"(f.x), "=f"(f.y) : "r"(h));
    return f;
}
__device__ __forceinline__ void split4(float4 v, unsigned& h0, unsigned& h1,
                                       unsigned& l0, unsigned& l1) {
    h0 = pack2h(v.x, v.y);
    h1 = pack2h(v.z, v.w);
    float2 f0 = h2f(h0), f1 = h2f(h1);
    l0 = pack2h(v.x - f0.x, v.y - f0.y);
    l1 = pack2h(v.z - f1.x, v.w - f1.y);
}
__device__ __forceinline__ void ldsm4(unsigned r[4], unsigned addr) {
    asm volatile("ldmatrix.sync.aligned.m8n8.x4.shared.b16 {%0,%1,%2,%3}, [%4];"
                 : "=r"(r[0]), "=r"(r[1]), "=r"(r[2]), "=r"(r[3]) : "r"(addr));
}
__device__ __forceinline__ void ldsm4t(unsigned r[4], unsigned addr) {
    asm volatile("ldmatrix.sync.aligned.m8n8.x4.trans.shared.b16 {%0,%1,%2,%3}, [%4];"
                 : "=r"(r[0]), "=r"(r[1]), "=r"(r[2]), "=r"(r[3]) : "r"(addr));
}
__device__ __forceinline__ void mma16(float c[4], const unsigned a[4],
                                      unsigned b0, unsigned b1) {
    asm volatile(
        "mma.sync.aligned.m16n8k16.row.col.f32.f16.f16.f32 "
        "{%0,%1,%2,%3},{%4,%5,%6,%7},{%8,%9},{%0,%1,%2,%3};"
        : "+f"(c[0]), "+f"(c[1]), "+f"(c[2]), "+f"(c[3])
        : "r"(a[0]), "r"(a[1]), "r"(a[2]), "r"(a[3]), "r"(b0), "r"(b1));
}
__device__ __forceinline__ void copy128(const float* __restrict__ s, float* __restrict__ d) {
    const float4* s4 = (const float4*)s;
    float4* d4 = (float4*)d;
#pragma unroll
    for (int i = threadIdx.x; i < DN * DN / 4; i += 256) d4[i] = s4[i];
}

// stage one k16 slab of fp16(Msrc - I) into smem [16][AROWB]
__device__ __forceinline__ void stageDh(const float* __restrict__ Msrc, int k0,
                                        char* sm, unsigned off, int tid) {
    const int r = tid >> 4, cc = (tid & 15) * 8;
    const int gr = k0 + r;
    const float* p = &Msrc[(size_t)gr * DN + cc];
    float4 v0 = *(const float4*)p, v1 = *(const float4*)(p + 4);
    v0.x -= (float)(gr == cc);     v0.y -= (float)(gr == cc + 1);
    v0.z -= (float)(gr == cc + 2); v0.w -= (float)(gr == cc + 3);
    v1.x -= (float)(gr == cc + 4); v1.y -= (float)(gr == cc + 5);
    v1.z -= (float)(gr == cc + 6); v1.w -= (float)(gr == cc + 7);
    *(uint4*)(sm + off + r * AROWB + cc * 2) =
        make_uint4(pack2h(v0.x, v0.y), pack2h(v0.z, v0.w),
                   pack2h(v1.x, v1.y), pack2h(v1.z, v1.w));
}

// acc += Ares[.., k0:k0+16] @ Bslab  (warp: 64x32 tile, 16 HMMA)
__device__ __forceinline__ void mma_slab(float acc[4][4][4], unsigned aB, unsigned bB,
                                         int k0, int wm, int wn, unsigned loff) {
    unsigned af[4][4];
#pragma unroll
    for (int mt = 0; mt < 4; mt++)
        ldsm4(af[mt], aB + (unsigned)((wm + mt * 16) * AROWB + k0 * 2) + loff);
    unsigned bf[2][4];
#pragma unroll
    for (int np = 0; np < 2; np++)
        ldsm4t(bf[np], bB + (unsigned)((wn + np * 16) * 2) + loff);
#pragma unroll
    for (int mt = 0; mt < 4; mt++)
#pragma unroll
        for (int nt = 0; nt < 4; nt++)
            mma16(acc[mt][nt], af[mt], bf[nt >> 1][(nt & 1) * 2],
                  bf[nt >> 1][(nt & 1) * 2 + 1]);
}

// ---------- Pass 1: chained local prefixes, D-form, 1-term MMA ----------
__global__ void __launch_bounds__(256, 2) k_pass1(const float* __restrict__ in,
                                                  float* __restrict__ outAll) {
    extern __shared__ char sm[];
    const int tid = threadIdx.x, lane = tid & 31, w = tid >> 5;
    const int wm = (w >> 2) * 64, wn = (w & 3) * 32;
    const unsigned smb = smem_u32(sm);
    const unsigned loff = (unsigned)(((lane & 7) + (lane & 8)) * AROWB + (lane >> 4) * 16);
    const int b = blockIdx.x / CH, c = blockIdx.x % CH;
    const size_t base = ((size_t)b * SEQ + (size_t)c * CL) * MM;
    const float* E = in + base;
    float* O = outAll + base;
    copy128(E, O);
    // resident Dp = E0 - I, hi/lo split
#pragma unroll
    for (int i = 0; i < 16; i++) {
        int f = tid + 256 * i, r = f >> 5, c4 = (f & 31) * 4;
        float4 v = *(const float4*)&E[(size_t)r * DN + c4];
        v.x -= (float)(r == c4);     v.y -= (float)(r == c4 + 1);
        v.z -= (float)(r == c4 + 2); v.w -= (float)(r == c4 + 3);
        unsigned h0, h1, l0, l1;
        split4(v, h0, h1, l0, l1);
        *(uint2*)(sm + OFF_PH + r * AROWB + c4 * 2) = make_uint2(h0, h1);
        *(uint2*)(sm + OFF_PL + r * AROWB + c4 * 2) = make_uint2(l0, l1);
    }
#pragma unroll 1
    for (int j = 1; j < CL; j++) {
        const float* Ej = E + (size_t)j * MM;
        float* Oj = O + (size_t)j * MM;
        float acc[4][4][4];
#pragma unroll
        for (int mt = 0; mt < 4; mt++)
#pragma unroll
            for (int nt = 0; nt < 4; nt++)
#pragma unroll
                for (int i = 0; i < 4; i++) acc[mt][nt][i] = 0.0f;
#pragma unroll 1
        for (int s = 0; s < 8; s++) {
            __syncthreads();  // prior slab ldsm / resident updates done
            stageDh(Ej, s * 16, sm, OFF_E1, tid);
            __syncthreads();
            mma_slab(acc, smb + OFF_PH, smb + OFF_E1, s * 16, wm, wn, loff);
        }
        __syncthreads();  // all resident-tile ldsm reads done before update
        // out = acc + Dp + Ej ;  Dp_new = out - I
#pragma unroll
        for (int mt = 0; mt < 4; mt++)
#pragma unroll
            for (int nt = 0; nt < 4; nt++) {
                const int r0 = wm + mt * 16 + (lane >> 2);
                const int c0 = wn + nt * 8 + (lane & 3) * 2;
#pragma unroll
                for (int hr = 0; hr < 2; hr++) {
                    const int r = r0 + hr * 8;
                    float a0 = acc[mt][nt][hr * 2], a1 = acc[mt][nt][hr * 2 + 1];
                    float2 ph = h2f(*(unsigned*)(sm + OFF_PH + r * AROWB + c0 * 2));
                    float2 pl = h2f(*(unsigned*)(sm + OFF_PL + r * AROWB + c0 * 2));
                    float2 e = *(const float2*)&Ej[(size_t)r * DN + c0];
                    float o0 = a0 + ph.x + pl.x + e.x;
                    float o1 = a1 + ph.y + pl.y + e.y;
                    *(float2*)&Oj[(size_t)r * DN + c0] = make_float2(o0, o1);
                    float d0 = o0 - (float)(r == c0), d1 = o1 - (float)(r == c0 + 1);
                    unsigned hh = pack2h(d0, d1);
                    float2 hf = h2f(hh);
                    unsigned ll = pack2h(d0 - hf.x, d1 - hf.y);
                    *(unsigned*)(sm + OFF_PH + r * AROWB + c0 * 2) = hh;
                    *(unsigned*)(sm + OFF_PL + r * AROWB + c0 * 2) = ll;
                }
            }
    }
}

// ---------- Pass 3: apply chunk prefix, D-form, 1-term MMA ----------
__global__ void __launch_bounds__(256, 2) k_pass3(float* __restrict__ outAll,
                                                  const float* __restrict__ scan) {
    extern __shared__ char sm[];
    const int tid = threadIdx.x, lane = tid & 31, w = tid >> 5;
    const int wm = (w >> 2) * 64, wn = (w & 3) * 32;
    const unsigned smb = smem_u32(sm);
    const unsigned loff = (unsigned)(((lane & 7) + (lane & 8)) * AROWB + (lane >> 4) * 16);
    int idx = blockIdx.x;
    const int j = idx % CL; idx /= CL;
    const int c = (idx % (CH - 1)) + 1; idx /= (CH - 1);
    const int b = idx;
    const float* Sc = scan + ((size_t)b * CH + (c - 1)) * MM;
    float* Bp = outAll + ((size_t)b * SEQ + (size_t)c * CL + j) * MM;
    // resident Dc = Sc - I (hi only)
#pragma unroll
    for (int i = 0; i < 16; i++) {
        int f = tid + 256 * i, r = f >> 5, c4 = (f & 31) * 4;
        float4 v = *(const float4*)&Sc[(size_t)r * DN + c4];
        v.x -= (float)(r == c4);     v.y -= (float)(r == c4 + 1);
        v.z -= (float)(r == c4 + 2); v.w -= (float)(r == c4 + 3);
        *(uint2*)(sm + OFF_CHI + r * AROWB + c4 * 2) =
            make_uint2(pack2h(v.x, v.y), pack2h(v.z, v.w));
    }
    float acc[4][4][4];
#pragma unroll
    for (int mt = 0; mt < 4; mt++)
#pragma unroll
        for (int nt = 0; nt < 4; nt++)
#pragma unroll
            for (int i = 0; i < 4; i++) acc[mt][nt][i] = 0.0f;
#pragma unroll 1
    for (int s = 0; s < 8; s++) {
        __syncthreads();  // (s=0: resident tile visible) prior slab ldsm done
        stageDh(Bp, s * 16, sm, OFF_E3, tid);
        __syncthreads();
        mma_slab(acc, smb + OFF_CHI, smb + OFF_E3, s * 16, wm, wn, loff);
    }
    // out = acc + Sc + Bp - I  (each element read+written by its own thread)
#pragma unroll
    for (int mt = 0; mt < 4; mt++)
#pragma unroll
        for (int nt = 0; nt < 4; nt++) {
            const int r0 = wm + mt * 16 + (lane >> 2);
            const int c0 = wn + nt * 8 + (lane & 3) * 2;
#pragma unroll
            for (int hr = 0; hr < 2; hr++) {
                const int r = r0 + hr * 8;
                float a0 = acc[mt][nt][hr * 2], a1 = acc[mt][nt][hr * 2 + 1];
                float2 sc = *(const float2*)&Sc[(size_t)r * DN + c0];
                float2 bl = *(const float2*)&Bp[(size_t)r * DN + c0];
                *(float2*)&Bp[(size_t)r * DN + c0] =
                    make_float2(a0 + sc.x + bl.x - (float)(r == c0),
                                a1 + sc.y + bl.y - (float)(r == c0 + 1));
            }
        }
}

// ---------- Pass 2: 3-term full-matrix core (proven R7 path) ----------
#define ASTRU 12
#define BSTRU 68
__device__ __forceinline__ void mm3(const float* __restrict__ A,
                                    const float* __restrict__ B,
                                    float* __restrict__ C) {
    __shared__ __align__(16) unsigned Ah[DN * ASTRU], Al[DN * ASTRU];
    __shared__ __align__(16) unsigned Bh[16 * BSTRU], Bl[16 * BSTRU];
    const int tid = threadIdx.x, lane = tid & 31, w = tid >> 5;
    const int wm = (w >> 2) * 64, wn = (w & 3) * 32;
    const int am = tid >> 1, aku = tid & 1;
    const int bk = tid >> 4, bn = (tid & 15) * 8;
    const unsigned aBaseH = smem_u32(Ah), aBaseL = smem_u32(Al);
    const unsigned bBaseH = smem_u32(Bh), bBaseL = smem_u32(Bl);
    const unsigned aoff = (unsigned)(((lane & 7) + (lane & 8)) * 48 + (lane >> 4) * 16);
    const unsigned boff = (unsigned)(((lane & 7) + (lane & 8)) * 272 + (lane >> 4) * 16);
    float acc[4][4][4];
#pragma unroll
    for (int mt = 0; mt < 4; mt++)
#pragma unroll
        for (int nt = 0; nt < 4; nt++)
#pragma unroll
            for (int i = 0; i < 4; i++) acc[mt][nt][i] = 0.0f;
    __syncthreads();
    float4 va0 = *(const float4*)&A[(size_t)am * DN + aku * 8];
    float4 va1 = *(const float4*)&A[(size_t)am * DN + aku * 8 + 4];
    float4 vb0 = *(const float4*)&B[(size_t)bk * DN + bn];
    float4 vb1 = *(const float4*)&B[(size_t)bk * DN + bn + 4];
    for (int s = 0; s < 8; s++) {
        unsigned h0, h1, l0, l1, h2, h3, l2, l3;
        split4(va0, h0, h1, l0, l1);
        split4(va1, h2, h3, l2, l3);
        *(uint4*)&Ah[am * ASTRU + aku * 4] = make_uint4(h0, h1, h2, h3);
        *(uint4*)&Al[am * ASTRU + aku * 4] = make_uint4(l0, l1, l2, l3);
        split4(vb0, h0, h1, l0, l1);
        split4(vb1, h2, h3, l2, l3);
        *(uint4*)&Bh[bk * BSTRU + (bn >> 1)] = make_uint4(h0, h1, h2, h3);
        *(uint4*)&Bl[bk * BSTRU + (bn >> 1)] = make_uint4(l0, l1, l2, l3);
        __syncthreads();
        if (s < 7) {
            const int k0 = (s + 1) * 16;
            va0 = *(const float4*)&A[(size_t)am * DN + k0 + aku * 8];
            va1 = *(const float4*)&A[(size_t)am * DN + k0 + aku * 8 + 4];
            vb0 = *(const float4*)&B[(size_t)(k0 + bk) * DN + bn];
            vb1 = *(const float4*)&B[(size_t)(k0 + bk) * DN + bn + 4];
        }
#pragma unroll
        for (int t = 0; t < 3; t++) {
            const unsigned aB = (t == 1) ? aBaseL : aBaseH;
            const unsigned bB = (t == 2) ? bBaseL : bBaseH;
            unsigned af[4][4];
#pragma unroll
            for (int mt = 0; mt < 4; mt++)
                ldsm4(af[mt], aB + (unsigned)((wm + mt * 16) * 48) + aoff);
            unsigned bf[2][4];
#pragma unroll
            for (int np = 0; np < 2; np++)
                ldsm4t(bf[np], bB + (unsigned)((wn + np * 16) * 2) + boff);
#pragma unroll
            for (int mt = 0; mt < 4; mt++)
#pragma unroll
                for (int nt = 0; nt < 4; nt++)
                    mma16(acc[mt][nt], af[mt], bf[nt >> 1][(nt & 1) * 2],
                          bf[nt >> 1][(nt & 1) * 2 + 1]);
        }
        __syncthreads();
    }
#pragma unroll
    for (int mt = 0; mt < 4; mt++)
#pragma unroll
        for (int nt = 0; nt < 4; nt++) {
            const int r0 = wm + mt * 16 + (lane >> 2);
            const int c0 = wn + nt * 8 + (lane & 3) * 2;
            *(float2*)&C[(size_t)r0 * DN + c0] = make_float2(acc[mt][nt][0], acc[mt][nt][1]);
            *(float2*)&C[(size_t)(r0 + 8) * DN + c0] = make_float2(acc[mt][nt][2], acc[mt][nt][3]);
        }
}

__global__ void __launch_bounds__(256, 2) k_scan(const float* __restrict__ src,
                                                 size_t soff, size_t sb, size_t si,
                                                 float* __restrict__ dst, int d) {
    const int b = blockIdx.x / CH, i = blockIdx.x % CH;
    const float* Ti = src + soff + (size_t)b * sb + (size_t)i * si;
    float* Dp = dst + ((size_t)b * CH + i) * MM;
    if (i < d) { copy128(Ti, Dp); return; }
    mm3(src + soff + (size_t)b * sb + (size_t)(i - d) * si, Ti, Dp);
}

__global__ void __launch_bounds__(256) k_copy_x(const float* __restrict__ outAll,
                                                float* __restrict__ x) {
    copy128(outAll + ((size_t)blockIdx.x * SEQ + (SEQ - 1)) * MM,
            x + (size_t)blockIdx.x * MM);
}

extern "C" void kernel_launch(void* const* d_in, const int* in_sizes, int n_in,
                              void* d_out, int out_size) {
    const float* in = (const float*)d_in[0];
    float* out = (float*)d_out;
    float* x = out;                                  // (32,128,128)
    float* outAll = out + (size_t)BATCH * MM;        // (32,256,128,128)

    float *scr0, *scr1;
    cudaGetSymbolAddress((void**)&scr0, g_scr0);
    cudaGetSymbolAddress((void**)&scr1, g_scr1);

    cudaFuncSetAttribute(k_pass1, cudaFuncAttributeMaxDynamicSharedMemorySize, P1_SMEM);
    cudaFuncSetAttribute(k_pass3, cudaFuncAttributeMaxDynamicSharedMemorySize, P3_SMEM);

    k_pass1<<<BATCH * CH, 256, P1_SMEM>>>(in, outAll);
    // Hillis-Steele over chunk totals (full matrices, 3-term core)
    k_scan<<<BATCH * CH, 256>>>(outAll, (size_t)(CL - 1) * MM,
                                (size_t)SEQ * MM, (size_t)CL * MM, scr0, 1);
    k_scan<<<BATCH * CH, 256>>>(scr0, 0, (size_t)CH * MM, MM, scr1, 2);
    k_scan<<<BATCH * CH, 256>>>(scr1, 0, (size_t)CH * MM, MM, scr0, 4);
    k_scan<<<BATCH * CH, 256>>>(scr0, 0, (size_t)CH * MM, MM, scr1, 8);
    k_pass3<<<BATCH * (CH - 1) * CL, 256, P3_SMEM>>>(outAll, scr1);
    k_copy_x<<<BATCH, 256>>>(outAll, x);
}

// round 16
// speedup vs baseline: 1.1908x; 1.1908x over previous
#include <cuda_runtime.h>
#include <cstdint>

// Cumulative matrix product over axis 1; inputs are I + 0.02*noise.
// Identity-subtracted chunked scan: pass1/pass3 compute only D_a @ D_b with
// fp16 MMA (pass1 1-term, pass3 2-term), double-buffered K=32 slabs with
// register prefetch. pass2 (chunk-total scan) uses the proven 3-term core.

#define DN 128
#define BATCH 32
#define SEQ 256
#define CH 16
#define CL 16
#define MM ((size_t)DN * DN)

#define AROWB 272u   // smem row: 128 halves + 8 pad (conflict-free ldmatrix)
#define OFF_RH 0u        // resident hi  (128 rows)
#define OFF_RL 34816u    // resident lo
#define OFF_B0 69632u    // B slab buf0 (32 rows)
#define OFF_B1 78336u    // B slab buf1
#define DP_SMEM 87040

__device__ float g_scr0[(size_t)BATCH * CH * DN * DN];
__device__ float g_scr1[(size_t)BATCH * CH * DN * DN];

__device__ __forceinline__ unsigned smem_u32(const void* p) {
    unsigned a;
    asm("{ .reg .u64 t; cvta.to.shared.u64 t, %1; cvt.u32.u64 %0, t; }" : "=r"(a) : "l"(p));
    return a;
}
__device__ __forceinline__ unsigned pack2h(float lo, float hi) {
    unsigned r;
    asm("cvt.rn.f16x2.f32 %0, %1, %2;" : "=r"(r) : "f"(hi), "f"(lo));
    return r;
}
__device__ __forceinline__ float2 h2f(unsigned h) {
    float2 f;
    asm("{ .reg .f16 a, b;\n\t mov.b32 {a, b}, %2;\n\t"
        " cvt.f32.f16 %0, a;\n\t cvt.f32.f16 %1, b; }"
        : "=f"(f.x), "=f"(f.y) : "r"(h));
    return f;
}
__device__ __forceinline__ void split4(float4 v, unsigned& h0, unsigned& h1,
                                       unsigned& l0, unsigned& l1) {
    h0 = pack2h(v.x, v.y);
    h1 = pack2h(v.z, v.w);
    float2 f0 = h2f(h0), f1 = h2f(h1);
    l0 = pack2h(v.x - f0.x, v.y - f0.y);
    l1 = pack2h(v.z - f1.x, v.w - f1.y);
}
__device__ __forceinline__ void ldsm4(unsigned r[4], unsigned addr) {
    asm volatile("ldmatrix.sync.aligned.m8n8.x4.shared.b16 {%0,%1,%2,%3}, [%4];"
                 : "=r"(r[0]), "=r"(r[1]), "=r"(r[2]), "=r"(r[3]) : "r"(addr));
}
__device__ __forceinline__ void ldsm4t(unsigned r[4], unsigned addr) {
    asm volatile("ldmatrix.sync.aligned.m8n8.x4.trans.shared.b16 {%0,%1,%2,%3}, [%4];"
                 : "=r"(r[0]), "=r"(r[1]), "=r"(r[2]), "=r"(r[3]) : "r"(addr));
}
__device__ __forceinline__ void mma16(float c[4], const unsigned a[4],
                                      unsigned b0, unsigned b1) {
    asm volatile(
        "mma.sync.aligned.m16n8k16.row.col.f32.f16.f16.f32 "
        "{%0,%1,%2,%3},{%4,%5,%6,%7},{%8,%9},{%0,%1,%2,%3};"
        : "+f"(c[0]), "+f"(c[1]), "+f"(c[2]), "+f"(c[3])
        : "r"(a[0]), "r"(a[1]), "r"(a[2]), "r"(a[3]), "r"(b0), "r"(b1));
}
__device__ __forceinline__ void copy128(const float* __restrict__ s, float* __restrict__ d) {
    const float4* s4 = (const float4*)s;
    float4* d4 = (float4*)d;
#pragma unroll
    for (int i = threadIdx.x; i < DN * DN / 4; i += 256) d4[i] = s4[i];
}

// prefetch one K=32 slab of raw floats (warp w handles rows w, w+8, w+16, w+24)
__device__ __forceinline__ void prefSlab(const float* __restrict__ M, int k0,
                                         int w, int lane, float4 rb[4]) {
#pragma unroll
    for (int i = 0; i < 4; i++)
        rb[i] = *(const float4*)&M[(size_t)(k0 + w + 8 * i) * DN + lane * 4];
}
// store slab as fp16(M - I), hi only, rows 0..31 of buffer (STS.64 conflict-free)
__device__ __forceinline__ void storeSlabD(char* sm, unsigned off, int k0,
                                           int w, int lane, const float4 rb[4]) {
#pragma unroll
    for (int i = 0; i < 4; i++) {
        const int r = w + 8 * i, gr = k0 + r, cc = lane * 4;
        float4 v = rb[i];
        v.x -= (float)(gr == cc);     v.y -= (float)(gr == cc + 1);
        v.z -= (float)(gr == cc + 2); v.w -= (float)(gr == cc + 3);
        *(uint2*)(sm + off + r * AROWB + cc * 2) =
            make_uint2(pack2h(v.x, v.y), pack2h(v.z, v.w));
    }
}
// acc += Ares[:, s*32 : s*32+32] @ Bslab   (warp 64x32 tile, 32 HMMA)
__device__ __forceinline__ void mma_slab32(float acc[4][4][4], unsigned aB, unsigned bB,
                                           int s, int wm, int wn, unsigned loff) {
#pragma unroll
    for (int kk = 0; kk < 32; kk += 16) {
        unsigned af[4][4];
#pragma unroll
        for (int mt = 0; mt < 4; mt++)
            ldsm4(af[mt], aB + (unsigned)((wm + mt * 16) * AROWB + (s * 32 + kk) * 2) + loff);
        unsigned bf[2][4];
#pragma unroll
        for (int np = 0; np < 2; np++)
            ldsm4t(bf[np], bB + (unsigned)(kk * AROWB + (wn + np * 16) * 2) + loff);
#pragma unroll
        for (int mt = 0; mt < 4; mt++)
#pragma unroll
            for (int nt = 0; nt < 4; nt++)
                mma16(acc[mt][nt], af[mt], bf[nt >> 1][(nt & 1) * 2],
                      bf[nt >> 1][(nt & 1) * 2 + 1]);
    }
}

// ---------- Pass 1: chained local prefixes, D-form, 1-term ----------
__global__ void __launch_bounds__(256, 2) k_pass1(const float* __restrict__ in,
                                                  float* __restrict__ outAll) {
    extern __shared__ char sm[];
    const int tid = threadIdx.x, lane = tid & 31, w = tid >> 5;
    const int wm = (w >> 2) * 64, wn = (w & 3) * 32;
    const unsigned smb = smem_u32(sm);
    const unsigned loff = (unsigned)(((lane & 7) + (lane & 8)) * AROWB + (lane >> 4) * 16);
    const int b = blockIdx.x / CH, c = blockIdx.x % CH;
    const size_t base = ((size_t)b * SEQ + (size_t)c * CL) * MM;
    const float* E = in + base;
    float* O = outAll + base;
    copy128(E, O);
    float4 rb[4];
    prefSlab(E + MM, 0, w, lane, rb);   // E1 slab 0 in flight during prologue
    // resident Dp = E0 - I, hi/lo
#pragma unroll
    for (int i = 0; i < 16; i++) {
        const int r = w + 8 * i, cc = lane * 4;
        float4 v = *(const float4*)&E[(size_t)r * DN + cc];
        v.x -= (float)(r == cc);     v.y -= (float)(r == cc + 1);
        v.z -= (float)(r == cc + 2); v.w -= (float)(r == cc + 3);
        unsigned h0, h1, l0, l1;
        split4(v, h0, h1, l0, l1);
        *(uint2*)(sm + OFF_RH + r * AROWB + cc * 2) = make_uint2(h0, h1);
        *(uint2*)(sm + OFF_RL + r * AROWB + cc * 2) = make_uint2(l0, l1);
    }
#pragma unroll 1
    for (int j = 1; j < CL; j++) {
        const float* Ej = E + (size_t)j * MM;
        float* Oj = O + (size_t)j * MM;
        float acc[4][4][4];
#pragma unroll
        for (int mt = 0; mt < 4; mt++)
#pragma unroll
            for (int nt = 0; nt < 4; nt++)
#pragma unroll
                for (int i = 0; i < 4; i++) acc[mt][nt][i] = 0.0f;
#pragma unroll 1
        for (int s = 0; s < 4; s++) {
            const unsigned bb = (s & 1) ? OFF_B1 : OFF_B0;
            storeSlabD(sm, bb, s * 32, w, lane, rb);
            __syncthreads();  // slab (and s==0: resident/epilogue) visible
            if (s < 3) prefSlab(Ej, (s + 1) * 32, w, lane, rb);
            else if (j < CL - 1) prefSlab(Ej + MM, 0, w, lane, rb);
            mma_slab32(acc, smb + OFF_RH, smb + bb, s, wm, wn, loff);
        }
        __syncthreads();  // all ldsm of resident done before update
        // out = acc + Dp + Ej ; Dp_new = out - I
#pragma unroll
        for (int mt = 0; mt < 4; mt++)
#pragma unroll
            for (int nt = 0; nt < 4; nt++) {
                const int r0 = wm + mt * 16 + (lane >> 2);
                const int c0 = wn + nt * 8 + (lane & 3) * 2;
#pragma unroll
                for (int hr = 0; hr < 2; hr++) {
                    const int r = r0 + hr * 8;
                    float a0 = acc[mt][nt][hr * 2], a1 = acc[mt][nt][hr * 2 + 1];
                    float2 ph = h2f(*(unsigned*)(sm + OFF_RH + r * AROWB + c0 * 2));
                    float2 pl = h2f(*(unsigned*)(sm + OFF_RL + r * AROWB + c0 * 2));
                    float2 e = *(const float2*)&Ej[(size_t)r * DN + c0];
                    float o0 = a0 + ph.x + pl.x + e.x;
                    float o1 = a1 + ph.y + pl.y + e.y;
                    *(float2*)&Oj[(size_t)r * DN + c0] = make_float2(o0, o1);
                    float d0 = o0 - (float)(r == c0), d1 = o1 - (float)(r == c0 + 1);
                    unsigned hh = pack2h(d0, d1);
                    float2 hf = h2f(hh);
                    unsigned ll = pack2h(d0 - hf.x, d1 - hf.y);
                    *(unsigned*)(sm + OFF_RH + r * AROWB + c0 * 2) = hh;
                    *(unsigned*)(sm + OFF_RL + r * AROWB + c0 * 2) = ll;
                }
            }
    }
}

// ---------- Pass 3: apply chunk prefix, D-form, 2-term ----------
__global__ void __launch_bounds__(256, 2) k_pass3(float* __restrict__ outAll,
                                                  const float* __restrict__ scan) {
    extern __shared__ char sm[];
    const int tid = threadIdx.x, lane = tid & 31, w = tid >> 5;
    const int wm = (w >> 2) * 64, wn = (w & 3) * 32;
    const unsigned smb = smem_u32(sm);
    const unsigned loff = (unsigned)(((lane & 7) + (lane & 8)) * AROWB + (lane >> 4) * 16);
    int idx = blockIdx.x;
    const int j = idx % CL; idx /= CL;
    const int c = (idx % (CH - 1)) + 1; idx /= (CH - 1);
    const int b = idx;
    const float* Sc = scan + ((size_t)b * CH + (c - 1)) * MM;
    float* Bp = outAll + ((size_t)b * SEQ + (size_t)c * CL + j) * MM;
    float4 rb[4];
    prefSlab(Bp, 0, w, lane, rb);
    // resident Dc = Sc - I, hi/lo
#pragma unroll
    for (int i = 0; i < 16; i++) {
        const int r = w + 8 * i, cc = lane * 4;
        float4 v = *(const float4*)&Sc[(size_t)r * DN + cc];
        v.x -= (float)(r == cc);     v.y -= (float)(r == cc + 1);
        v.z -= (float)(r == cc + 2); v.w -= (float)(r == cc + 3);
        unsigned h0, h1, l0, l1;
        split4(v, h0, h1, l0, l1);
        *(uint2*)(sm + OFF_RH + r * AROWB + cc * 2) = make_uint2(h0, h1);
        *(uint2*)(sm + OFF_RL + r * AROWB + cc * 2) = make_uint2(l0, l1);
    }
    float acc[4][4][4];
#pragma unroll
    for (int mt = 0; mt < 4; mt++)
#pragma unroll
        for (int nt = 0; nt < 4; nt++)
#pragma unroll
            for (int i = 0; i < 4; i++) acc[mt][nt][i] = 0.0f;
#pragma unroll 1
    for (int s = 0; s < 4; s++) {
        const unsigned bb = (s & 1) ? OFF_B1 : OFF_B0;
        storeSlabD(sm, bb, s * 32, w, lane, rb);
        __syncthreads();
        if (s < 3) prefSlab(Bp, (s + 1) * 32, w, lane, rb);
        mma_slab32(acc, smb + OFF_RH, smb + bb, s, wm, wn, loff);   // Dc_hi * Db
        mma_slab32(acc, smb + OFF_RL, smb + bb, s, wm, wn, loff);   // Dc_lo * Db
    }
    // out = acc + Sc + Bp - I (each element owned by one thread)
#pragma unroll
    for (int mt = 0; mt < 4; mt++)
#pragma unroll
        for (int nt = 0; nt < 4; nt++) {
            const int r0 = wm + mt * 16 + (lane >> 2);
            const int c0 = wn + nt * 8 + (lane & 3) * 2;
#pragma unroll
            for (int hr = 0; hr < 2; hr++) {
                const int r = r0 + hr * 8;
                float a0 = acc[mt][nt][hr * 2], a1 = acc[mt][nt][hr * 2 + 1];
                float2 sc = *(const float2*)&Sc[(size_t)r * DN + c0];
                float2 bl = *(const float2*)&Bp[(size_t)r * DN + c0];
                *(float2*)&Bp[(size_t)r * DN + c0] =
                    make_float2(a0 + sc.x + bl.x - (float)(r == c0),
                                a1 + sc.y + bl.y - (float)(r == c0 + 1));
            }
        }
}

// ---------- Pass 2: 3-term full-matrix core (proven) ----------
#define ASTRU 12
#define BSTRU 68
__device__ __forceinline__ void mm3(const float* __restrict__ A,
                                    const float* __restrict__ B,
                                    float* __restrict__ C) {
    __shared__ __align__(16) unsigned Ah[DN * ASTRU], Al[DN * ASTRU];
    __shared__ __align__(16) unsigned Bh[16 * BSTRU], Bl[16 * BSTRU];
    const int tid = threadIdx.x, lane = tid & 31, w = tid >> 5;
    const int wm = (w >> 2) * 64, wn = (w & 3) * 32;
    const int am = tid >> 1, aku = tid & 1;
    const int bk = tid >> 4, bn = (tid & 15) * 8;
    const unsigned aBaseH = smem_u32(Ah), aBaseL = smem_u32(Al);
    const unsigned bBaseH = smem_u32(Bh), bBaseL = smem_u32(Bl);
    const unsigned aoff = (unsigned)(((lane & 7) + (lane & 8)) * 48 + (lane >> 4) * 16);
    const unsigned boff = (unsigned)(((lane & 7) + (lane & 8)) * 272 + (lane >> 4) * 16);
    float acc[4][4][4];
#pragma unroll
    for (int mt = 0; mt < 4; mt++)
#pragma unroll
        for (int nt = 0; nt < 4; nt++)
#pragma unroll
            for (int i = 0; i < 4; i++) acc[mt][nt][i] = 0.0f;
    __syncthreads();
    float4 va0 = *(const float4*)&A[(size_t)am * DN + aku * 8];
    float4 va1 = *(const float4*)&A[(size_t)am * DN + aku * 8 + 4];
    float4 vb0 = *(const float4*)&B[(size_t)bk * DN + bn];
    float4 vb1 = *(const float4*)&B[(size_t)bk * DN + bn + 4];
    for (int s = 0; s < 8; s++) {
        unsigned h0, h1, l0, l1, h2, h3, l2, l3;
        split4(va0, h0, h1, l0, l1);
        split4(va1, h2, h3, l2, l3);
        *(uint4*)&Ah[am * ASTRU + aku * 4] = make_uint4(h0, h1, h2, h3);
        *(uint4*)&Al[am * ASTRU + aku * 4] = make_uint4(l0, l1, l2, l3);
        split4(vb0, h0, h1, l0, l1);
        split4(vb1, h2, h3, l2, l3);
        *(uint4*)&Bh[bk * BSTRU + (bn >> 1)] = make_uint4(h0, h1, h2, h3);
        *(uint4*)&Bl[bk * BSTRU + (bn >> 1)] = make_uint4(l0, l1, l2, l3);
        __syncthreads();
        if (s < 7) {
            const int k0 = (s + 1) * 16;
            va0 = *(const float4*)&A[(size_t)am * DN + k0 + aku * 8];
            va1 = *(const float4*)&A[(size_t)am * DN + k0 + aku * 8 + 4];
            vb0 = *(const float4*)&B[(size_t)(k0 + bk) * DN + bn];
            vb1 = *(const float4*)&B[(size_t)(k0 + bk) * DN + bn + 4];
        }
#pragma unroll
        for (int t = 0; t < 3; t++) {
            const unsigned aB = (t == 1) ? aBaseL : aBaseH;
            const unsigned bB = (t == 2) ? bBaseL : bBaseH;
            unsigned af[4][4];
#pragma unroll
            for (int mt = 0; mt < 4; mt++)
                ldsm4(af[mt], aB + (unsigned)((wm + mt * 16) * 48) + aoff);
            unsigned bf[2][4];
#pragma unroll
            for (int np = 0; np < 2; np++)
                ldsm4t(bf[np], bB + (unsigned)((wn + np * 16) * 2) + boff);
#pragma unroll
            for (int mt = 0; mt < 4; mt++)
#pragma unroll
                for (int nt = 0; nt < 4; nt++)
                    mma16(acc[mt][nt], af[mt], bf[nt >> 1][(nt & 1) * 2],
                          bf[nt >> 1][(nt & 1) * 2 + 1]);
        }
        __syncthreads();
    }
#pragma unroll
    for (int mt = 0; mt < 4; mt++)
#pragma unroll
        for (int nt = 0; nt < 4; nt++) {
            const int r0 = wm + mt * 16 + (lane >> 2);
            const int c0 = wn + nt * 8 + (lane & 3) * 2;
            *(float2*)&C[(size_t)r0 * DN + c0] = make_float2(acc[mt][nt][0], acc[mt][nt][1]);
            *(float2*)&C[(size_t)(r0 + 8) * DN + c0] = make_float2(acc[mt][nt][2], acc[mt][nt][3]);
        }
}

__global__ void __launch_bounds__(256, 2) k_scan(const float* __restrict__ src,
                                                 size_t soff, size_t sb, size_t si,
                                                 float* __restrict__ dst, int d) {
    const int b = blockIdx.x / CH, i = blockIdx.x % CH;
    const float* Ti = src + soff + (size_t)b * sb + (size_t)i * si;
    float* Dp = dst + ((size_t)b * CH + i) * MM;
    if (i < d) { copy128(Ti, Dp); return; }
    mm3(src + soff + (size_t)b * sb + (size_t)(i - d) * si, Ti, Dp);
}

__global__ void __launch_bounds__(256) k_copy_x(const float* __restrict__ outAll,
                                                float* __restrict__ x) {
    copy128(outAll + ((size_t)blockIdx.x * SEQ + (SEQ - 1)) * MM,
            x + (size_t)blockIdx.x * MM);
}

extern "C" void kernel_launch(void* const* d_in, const int* in_sizes, int n_in,
                              void* d_out, int out_size) {
    const float* in = (const float*)d_in[0];
    float* out = (float*)d_out;
    float* x = out;                                  // (32,128,128)
    float* outAll = out + (size_t)BATCH * MM;        // (32,256,128,128)

    float *scr0, *scr1;
    cudaGetSymbolAddress((void**)&scr0, g_scr0);
    cudaGetSymbolAddress((void**)&scr1, g_scr1);

    cudaFuncSetAttribute(k_pass1, cudaFuncAttributeMaxDynamicSharedMemorySize, DP_SMEM);
    cudaFuncSetAttribute(k_pass3, cudaFuncAttributeMaxDynamicSharedMemorySize, DP_SMEM);

    k_pass1<<<BATCH * CH, 256, DP_SMEM>>>(in, outAll);
    k_scan<<<BATCH * CH, 256>>>(outAll, (size_t)(CL - 1) * MM,
                                (size_t)SEQ * MM, (size_t)CL * MM, scr0, 1);
    k_scan<<<BATCH * CH, 256>>>(scr0, 0, (size_t)CH * MM, MM, scr1, 2);
    k_scan<<<BATCH * CH, 256>>>(scr1, 0, (size_t)CH * MM, MM, scr0, 4);
    k_scan<<<BATCH * CH, 256>>>(scr0, 0, (size_t)CH * MM, MM, scr1, 8);
    k_pass3<<<BATCH * (CH - 1) * CL, 256, DP_SMEM>>>(outAll, scr1);
    k_copy_x<<<BATCH, 256>>>(outAll, x);
}